// round 6
// baseline (speedup 1.0000x reference)
#include <cuda_runtime.h>
#include <cstdint>

// Problem shape (fixed by the dataset)
constexpr int Bc = 8, Hc = 16, Mc = 1024, Nc = 1024, Dc = 64;
constexpr int BHc = Bc * Hc;
constexpr long long OUT_ELEMS = (long long)BHc * Mc * Dc;   // 8,388,608
constexpr long long P_ELEMS   = (long long)BHc * Mc * Nc;   // 134,217,728

constexpr int MT = 32;        // M rows per CTA
constexpr int THREADS = 256;  // 8 warps, 3 CTAs/SM

#define NEG_INF_F (-1e9f)

__device__ __forceinline__ uint32_t tf32_hi(float x) {
    uint32_t h;
    asm("cvt.rna.tf32.f32 %0, %1;" : "=r"(h) : "f"(x));
    return h;
}

__device__ __forceinline__ void tf32_split(float x, uint32_t& h, uint32_t& l) {
    asm("cvt.rna.tf32.f32 %0, %1;" : "=r"(h) : "f"(x));
    float hf = __uint_as_float(h);
    float r  = x - hf;
    asm("cvt.rna.tf32.f32 %0, %1;" : "=r"(l) : "f"(r));
}

__device__ __forceinline__ void mma_tf32(float* c, const uint32_t* a, uint32_t b0, uint32_t b1) {
    asm volatile(
        "mma.sync.aligned.m16n8k8.row.col.f32.tf32.tf32.f32 "
        "{%0,%1,%2,%3}, {%4,%5,%6,%7}, {%8,%9}, {%0,%1,%2,%3};\n"
        : "+f"(c[0]), "+f"(c[1]), "+f"(c[2]), "+f"(c[3])
        : "r"(a[0]), "r"(a[1]), "r"(a[2]), "r"(a[3]), "r"(b0), "r"(b1));
}

__global__ __launch_bounds__(THREADS, 3)
void attn_tc_kernel(const float* __restrict__ q,
                    const float* __restrict__ k,
                    const float* __restrict__ v,
                    const int*   __restrict__ mask,
                    float* __restrict__ outp,   // may be null
                    float* __restrict__ pp)     // S scratch + p_attn output
{
    __shared__ float Red[6144];   // phase-3 k-split reduce
    __shared__ int   Msk[Nc];

    const int mtiles = Mc / MT;
    const int bh = blockIdx.x / mtiles;
    const int m0 = (blockIdx.x % mtiles) * MT;
    const int tid  = threadIdx.x;
    const int wid  = tid >> 5;       // 0..7
    const int lane = tid & 31;
    const int g = lane >> 2;         // 0..7
    const int t = lane & 3;          // 0..3

    const float scale = 1.0f / 32.0f;  // 1/sqrt(N=1024), faithful to the source bug

    float* Sbase = pp + ((size_t)bh * Mc + m0) * Nc;   // this CTA's 32 rows of p_attn

    #pragma unroll
    for (int i = 0; i < Nc / THREADS; i++)
        Msk[i * THREADS + tid] = mask[(size_t)bh * Nc + i * THREADS + tid];

    // =================== phase 1: S = mask(scale(Q K^T)), 2xTF32 ===============
    // warp = (mi, nbp): mi = m-half (16 rows), nbp -> n-slice [nbp*32,+32) per 128-block
    const int mi  = wid & 1;
    const int nbp = wid >> 1;

    // hoist Q-hi fragments for the full k=64 (32 regs)
    uint32_t ah[8][4];
    {
        const float* qb = q + ((size_t)(bh * Mc + m0) + mi * 16) * Dc;
        #pragma unroll
        for (int kc = 0; kc < 8; kc++) {
            ah[kc][0] = tf32_hi(qb[g * Dc + kc * 8 + t]);
            ah[kc][1] = tf32_hi(qb[(g + 8) * Dc + kc * 8 + t]);
            ah[kc][2] = tf32_hi(qb[g * Dc + kc * 8 + t + 4]);
            ah[kc][3] = tf32_hi(qb[(g + 8) * Dc + kc * 8 + t + 4]);
        }
    }
    __syncthreads();   // Msk ready

    const float* kbase = k + (size_t)bh * Nc * Dc;
    #pragma unroll 1
    for (int nt = 0; nt < 8; nt++) {
        float acc[4][4] = {};
        #pragma unroll
        for (int kc = 0; kc < 8; kc++) {
            #pragma unroll
            for (int nb = 0; nb < 4; nb++) {
                const float* kb = kbase +
                    (size_t)(nt * 128 + nbp * 32 + nb * 8 + g) * Dc + kc * 8;
                uint32_t bh0, bl0, bh1, bl1;
                tf32_split(kb[t],     bh0, bl0);
                tf32_split(kb[t + 4], bh1, bl1);
                mma_tf32(acc[nb], ah[kc], bh0, bh1);   // q_hi * k_hi
                mma_tf32(acc[nb], ah[kc], bl0, bl1);   // q_hi * k_lo
            }
        }
        #pragma unroll
        for (int nb = 0; nb < 4; nb++) {
            const int m = mi * 16 + g;
            const int n = nt * 128 + nbp * 32 + nb * 8 + 2 * t;
            const bool ok0 = Msk[n] != 0;
            const bool ok1 = Msk[n + 1] != 0;
            float s00 = ok0 ? acc[nb][0] * scale : NEG_INF_F;
            float s01 = ok1 ? acc[nb][1] * scale : NEG_INF_F;
            float s10 = ok0 ? acc[nb][2] * scale : NEG_INF_F;
            float s11 = ok1 ? acc[nb][3] * scale : NEG_INF_F;
            *(float2*)(Sbase + (size_t)m * Nc + n)       = make_float2(s00, s01);
            *(float2*)(Sbase + (size_t)(m + 8) * Nc + n) = make_float2(s10, s11);
        }
    }
    __syncthreads();

    // =================== phase 2: register-resident softmax (rows in gmem/L2) ==
    // warp wid owns rows wid*4 .. wid*4+3
    #pragma unroll 1
    for (int rr = 0; rr < 4; rr++) {
        const int m = wid * 4 + rr;
        float* prow = Sbase + (size_t)m * Nc;
        float r[32];
        float mx = NEG_INF_F;
        #pragma unroll
        for (int i = 0; i < 32; i++) {
            r[i] = prow[i * 32 + lane];
            mx = fmaxf(mx, r[i]);
        }
        #pragma unroll
        for (int o = 16; o; o >>= 1) mx = fmaxf(mx, __shfl_xor_sync(0xffffffffu, mx, o));
        float sum = 0.0f;
        #pragma unroll
        for (int i = 0; i < 32; i++) { r[i] = __expf(r[i] - mx); sum += r[i]; }
        #pragma unroll
        for (int o = 16; o; o >>= 1) sum += __shfl_xor_sync(0xffffffffu, sum, o);
        const float inv = 1.0f / sum;
        #pragma unroll
        for (int i = 0; i < 32; i++)
            prow[i * 32 + lane] = r[i] * inv;   // final p_attn, coalesced
    }
    __syncthreads();

    // =================== phase 3: out = P V (2xTF32, k-quarter split) ==========
    // warp = (mi3, kq): mi3 = m-half, kq = quarter of N; full d=64 per warp
    const int mi3 = wid & 1;
    const int kq  = wid >> 1;
    const float* vbase = v + (size_t)bh * Nc * Dc;

    float oacc[8][4] = {};   // [db][frag]
    #pragma unroll 2
    for (int kk = kq * 256; kk < kq * 256 + 256; kk += 8) {
        // A fragment: p from gmem (L2-hot), full split (p_hi + p_lo)
        const float* pb = Sbase + (size_t)(mi3 * 16 + g) * Nc + kk;
        uint32_t pah[4], pal[4];
        tf32_split(pb[t],              pah[0], pal[0]);
        tf32_split(pb[8 * Nc + t],     pah[1], pal[1]);
        tf32_split(pb[t + 4],          pah[2], pal[2]);
        tf32_split(pb[8 * Nc + t + 4], pah[3], pal[3]);
        const float* vb0 = vbase + (size_t)(kk + t) * Dc;
        const float* vb1 = vbase + (size_t)(kk + t + 4) * Dc;
        #pragma unroll
        for (int db = 0; db < 8; db++) {
            uint32_t vh0 = tf32_hi(vb0[db * 8 + g]);
            uint32_t vh1 = tf32_hi(vb1[db * 8 + g]);
            mma_tf32(oacc[db], pah, vh0, vh1);   // p_hi * v_hi
            mma_tf32(oacc[db], pal, vh0, vh1);   // p_lo * v_hi
        }
    }
    __syncthreads();
    // k-quarter reduce: kq 1..3 publish, kq 0 sums and stores out
    if (kq != 0) {
        #pragma unroll
        for (int db = 0; db < 8; db++)
            *(float4*)(&Red[((mi3 * 3 + (kq - 1)) * 8 + db) * 128 + lane * 4]) =
                make_float4(oacc[db][0], oacc[db][1], oacc[db][2], oacc[db][3]);
    }
    __syncthreads();
    if (kq == 0 && outp) {
        #pragma unroll
        for (int db = 0; db < 8; db++) {
            float4 r1 = *(float4*)(&Red[((mi3 * 3 + 0) * 8 + db) * 128 + lane * 4]);
            float4 r2 = *(float4*)(&Red[((mi3 * 3 + 1) * 8 + db) * 128 + lane * 4]);
            float4 r3 = *(float4*)(&Red[((mi3 * 3 + 2) * 8 + db) * 128 + lane * 4]);
            const int m = mi3 * 16 + g;
            float* ob = outp + ((size_t)bh * Mc + m0 + m) * Dc + db * 8 + 2 * t;
            *(float2*)ob = make_float2(oacc[db][0] + r1.x + r2.x + r3.x,
                                       oacc[db][1] + r1.y + r2.y + r3.y);
            *(float2*)(ob + 8 * Dc) = make_float2(oacc[db][2] + r1.z + r2.z + r3.z,
                                                  oacc[db][3] + r1.w + r2.w + r3.w);
        }
    }
}

extern "C" void kernel_launch(void* const* d_in, const int* in_sizes, int n_in,
                              void* d_out, int out_size)
{
    const float* q    = (const float*)d_in[0];
    const float* k    = (const float*)d_in[1];
    const float* v    = (const float*)d_in[2];
    const int*   mask = (const int*)d_in[3];

    float* outp = nullptr;
    float* pp   = nullptr;
    long long osz = (long long)out_size;
    if (osz >= OUT_ELEMS + P_ELEMS) {            // (out, p_attn) concatenated
        outp = (float*)d_out;
        pp   = (float*)d_out + OUT_ELEMS;
    } else {                                     // p_attn only
        pp   = (float*)d_out;
    }

    dim3 grid(BHc * (Mc / MT));   // 4096 CTAs; consecutive CTAs share (b,h) -> K/V L2 reuse
    attn_tc_kernel<<<grid, THREADS>>>(q, k, v, mask, outp, pp);
}

// round 7
// speedup vs baseline: 1.6345x; 1.6345x over previous
#include <cuda_runtime.h>
#include <cstdint>

// Problem shape (fixed by the dataset)
constexpr int Bc = 8, Hc = 16, Mc = 1024, Nc = 1024, Dc = 64;
constexpr int BHc = Bc * Hc;
constexpr long long OUT_ELEMS = (long long)BHc * Mc * Dc;   // 8,388,608
constexpr long long P_ELEMS   = (long long)BHc * Mc * Nc;   // 134,217,728

constexpr int MT = 32;        // M rows per CTA
constexpr int NTILE = 128;    // K/V/P rows (cols) per staged block
constexpr int THREADS = 256;  // 8 warps, 3 CTAs/SM

// smem pitches (floats) for conflict-free fragment access:
//  "(row g)*pitch + t" pattern needs pitch%32==4  (banks 4g+t distinct)
//  "(row t)*pitch + g" pattern needs pitch%32==8  (banks 8t+g distinct)
constexpr int KP = 68;   // K tile (also Q staging)
constexpr int VP = 72;   // V tile
constexpr int PP = 132;  // P block (132 % 32 == 4)

constexpr int KV_OFF = 0;                      // 128*72 = 9216 floats (K/V tile; Red alias)
constexpr int P_OFF  = KV_OFF + NTILE * VP;    // 32*132 = 4224 floats (P block / unused ph1)
constexpr int MSK_OFF = P_OFF + MT * PP;       // 1024 ints
constexpr int SMEM_FLOATS = MSK_OFF + Nc;      // 14464
constexpr size_t SMEM_BYTES = (size_t)SMEM_FLOATS * 4;   // 57,856 B -> 3 CTAs/SM

#define NEG_INF_F (-1e9f)

__device__ __forceinline__ uint32_t tf32_hi(float x) {
    uint32_t h;
    asm("cvt.rna.tf32.f32 %0, %1;" : "=r"(h) : "f"(x));
    return h;
}

__device__ __forceinline__ void tf32_split(float x, uint32_t& h, uint32_t& l) {
    asm("cvt.rna.tf32.f32 %0, %1;" : "=r"(h) : "f"(x));
    float hf = __uint_as_float(h);
    float r  = x - hf;
    asm("cvt.rna.tf32.f32 %0, %1;" : "=r"(l) : "f"(r));
}

__device__ __forceinline__ void mma_tf32(float* c, const uint32_t* a, uint32_t b0, uint32_t b1) {
    asm volatile(
        "mma.sync.aligned.m16n8k8.row.col.f32.tf32.tf32.f32 "
        "{%0,%1,%2,%3}, {%4,%5,%6,%7}, {%8,%9}, {%0,%1,%2,%3};\n"
        : "+f"(c[0]), "+f"(c[1]), "+f"(c[2]), "+f"(c[3])
        : "r"(a[0]), "r"(a[1]), "r"(a[2]), "r"(a[3]), "r"(b0), "r"(b1));
}

__global__ __launch_bounds__(THREADS, 3)
void attn_tc_kernel(const float* __restrict__ q,
                    const float* __restrict__ k,
                    const float* __restrict__ v,
                    const int*   __restrict__ mask,
                    float* __restrict__ outp,   // may be null
                    float* __restrict__ pp)     // S scratch + p_attn output
{
    extern __shared__ float smem[];
    float* KV  = smem + KV_OFF;    // K tile [128][KP] / V tile [128][VP] / Red alias
    float* Pb  = smem + P_OFF;     // P block [MT][PP] (phase 3)
    int*   Msk = (int*)(smem + MSK_OFF);

    const int mtiles = Mc / MT;
    const int bh = blockIdx.x / mtiles;
    const int m0 = (blockIdx.x % mtiles) * MT;
    const int tid  = threadIdx.x;
    const int wid  = tid >> 5;       // 0..7
    const int lane = tid & 31;
    const int g = lane >> 2;         // 0..7
    const int t = lane & 3;          // 0..3

    const float scale = 1.0f / 32.0f;  // 1/sqrt(N=1024), faithful to the source bug

    float* Sbase = pp + ((size_t)bh * Mc + m0) * Nc;   // this CTA's 32 rows of p_attn

    #pragma unroll
    for (int i = 0; i < Nc / THREADS; i++)
        Msk[i * THREADS + tid] = mask[(size_t)bh * Nc + i * THREADS + tid];

    // ---- stage Q tile into KV (pitch KP), hoist Q-hi fragments to registers ----
    {
        const float4* qg = (const float4*)(q + (size_t)(bh * Mc + m0) * Dc);
        #pragma unroll
        for (int i = 0; i < (MT * Dc / 4) / THREADS; i++) {
            int f4 = i * THREADS + tid;
            float4 val = qg[f4];
            int row = f4 >> 4;          // 16 float4 per 64-float row
            int c   = (f4 & 15) * 4;
            *(float4*)(KV + row * KP + c) = val;
        }
    }
    __syncthreads();

    // warp = (mi, nbp): mi = m-half (16 rows), nbp -> n-slice [nbp*32,+32) per 128-block
    const int mi  = wid & 1;
    const int nbp = wid >> 1;

    uint32_t ah[8][4];   // Q-hi fragments, full k=64
    {
        const float* qs = KV + (mi * 16) * KP;
        #pragma unroll
        for (int kc = 0; kc < 8; kc++) {
            ah[kc][0] = tf32_hi(qs[g * KP + kc * 8 + t]);
            ah[kc][1] = tf32_hi(qs[(g + 8) * KP + kc * 8 + t]);
            ah[kc][2] = tf32_hi(qs[g * KP + kc * 8 + t + 4]);
            ah[kc][3] = tf32_hi(qs[(g + 8) * KP + kc * 8 + t + 4]);
        }
    }

    // =================== phase 1: S = mask(scale(Q K^T)), 2xTF32 ===============
    const float* kbase = k + (size_t)bh * Nc * Dc;
    #pragma unroll 1
    for (int nt = 0; nt < Nc / NTILE; nt++) {
        __syncthreads();
        {   // stage K tile [128][64] -> KV pitch KP (coalesced)
            const float4* kg = (const float4*)(kbase + (size_t)nt * NTILE * Dc);
            #pragma unroll
            for (int i = 0; i < (NTILE * Dc / 4) / THREADS; i++) {
                int f4 = i * THREADS + tid;
                float4 val = kg[f4];
                int row = f4 >> 4;
                int c   = (f4 & 15) * 4;
                *(float4*)(KV + row * KP + c) = val;
            }
        }
        __syncthreads();

        float acc[4][4] = {};   // [nb][frag]
        #pragma unroll
        for (int kc = 0; kc < 8; kc++) {
            #pragma unroll
            for (int nb = 0; nb < 4; nb++) {
                const float* kb = KV + (nbp * 32 + nb * 8 + g) * KP + kc * 8;
                uint32_t bh0, bl0, bh1, bl1;
                tf32_split(kb[t],     bh0, bl0);
                tf32_split(kb[t + 4], bh1, bl1);
                mma_tf32(acc[nb], ah[kc], bh0, bh1);   // q_hi * k_hi
                mma_tf32(acc[nb], ah[kc], bl0, bl1);   // q_hi * k_lo
            }
        }
        #pragma unroll
        for (int nb = 0; nb < 4; nb++) {
            const int m = mi * 16 + g;
            const int n = nt * NTILE + nbp * 32 + nb * 8 + 2 * t;
            const bool ok0 = Msk[n] != 0;
            const bool ok1 = Msk[n + 1] != 0;
            float s00 = ok0 ? acc[nb][0] * scale : NEG_INF_F;
            float s01 = ok1 ? acc[nb][1] * scale : NEG_INF_F;
            float s10 = ok0 ? acc[nb][2] * scale : NEG_INF_F;
            float s11 = ok1 ? acc[nb][3] * scale : NEG_INF_F;
            *(float2*)(Sbase + (size_t)m * Nc + n)       = make_float2(s00, s01);
            *(float2*)(Sbase + (size_t)(m + 8) * Nc + n) = make_float2(s10, s11);
        }
    }
    __syncthreads();

    // =================== phase 2: register-resident softmax (rows in L2) =======
    // warp wid owns rows wid*4 .. wid*4+3
    #pragma unroll 1
    for (int rr = 0; rr < 4; rr++) {
        const int m = wid * 4 + rr;
        float* prow = Sbase + (size_t)m * Nc;
        float r[32];
        float mx = NEG_INF_F;
        #pragma unroll
        for (int i = 0; i < 32; i++) {
            r[i] = prow[i * 32 + lane];
            mx = fmaxf(mx, r[i]);
        }
        #pragma unroll
        for (int o = 16; o; o >>= 1) mx = fmaxf(mx, __shfl_xor_sync(0xffffffffu, mx, o));
        float sum = 0.0f;
        #pragma unroll
        for (int i = 0; i < 32; i++) { r[i] = __expf(r[i] - mx); sum += r[i]; }
        #pragma unroll
        for (int o = 16; o; o >>= 1) sum += __shfl_xor_sync(0xffffffffu, sum, o);
        const float inv = 1.0f / sum;
        #pragma unroll
        for (int i = 0; i < 32; i++)
            prow[i * 32 + lane] = r[i] * inv;   // final p_attn, coalesced
    }
    __syncthreads();

    // =================== phase 3: out = P V (2xTF32, k-quarter split) ==========
    // warp = (mi3, kq): mi3 = m-half, kq = k-quarter of each 128-block; full d=64
    const int mi3 = wid & 1;
    const int kq  = wid >> 1;
    const float* vbase = v + (size_t)bh * Nc * Dc;

    float oacc[8][4] = {};   // [db][frag]
    #pragma unroll 1
    for (int nt = 0; nt < Nc / NTILE; nt++) {
        __syncthreads();
        {   // stage V tile [128][64] -> KV pitch VP (coalesced)
            const float4* vg = (const float4*)(vbase + (size_t)nt * NTILE * Dc);
            #pragma unroll
            for (int i = 0; i < (NTILE * Dc / 4) / THREADS; i++) {
                int f4 = i * THREADS + tid;
                float4 val = vg[f4];
                int row = f4 >> 4;
                int c   = (f4 & 15) * 4;
                *(float4*)(KV + row * VP + c) = val;
            }
        }
        {   // stage P block [32 rows][128 cols] -> Pb pitch PP (coalesced L2 reads)
            #pragma unroll
            for (int i = 0; i < (MT * NTILE / 4) / THREADS; i++) {
                int f4 = i * THREADS + tid;
                int row = f4 >> 5;          // 32 float4 per 128-col row
                int c   = (f4 & 31) * 4;
                float4 val = *(const float4*)(Sbase + (size_t)row * Nc + nt * NTILE + c);
                *(float4*)(Pb + row * PP + c) = val;
            }
        }
        __syncthreads();

        #pragma unroll
        for (int kc = 0; kc < 4; kc++) {
            const int kk = kq * 32 + kc * 8;   // row within staged block
            const float* pb = Pb + (mi3 * 16 + g) * PP + kk;
            uint32_t pah[4], pal[4];
            tf32_split(pb[t],              pah[0], pal[0]);
            tf32_split(pb[8 * PP + t],     pah[1], pal[1]);
            tf32_split(pb[t + 4],          pah[2], pal[2]);
            tf32_split(pb[8 * PP + t + 4], pah[3], pal[3]);
            #pragma unroll
            for (int db = 0; db < 8; db++) {
                const int base = (kk + t) * VP + db * 8 + g;
                uint32_t vh0 = tf32_hi(KV[base]);
                uint32_t vh1 = tf32_hi(KV[base + 4 * VP]);
                mma_tf32(oacc[db], pah, vh0, vh1);   // p_hi * v_hi
                mma_tf32(oacc[db], pal, vh0, vh1);   // p_lo * v_hi
            }
        }
    }
    __syncthreads();
    // k-quarter reduce through Red (aliases KV; V tile dead now)
    float* Red = KV;
    if (kq != 0) {
        #pragma unroll
        for (int db = 0; db < 8; db++)
            *(float4*)(&Red[((mi3 * 3 + (kq - 1)) * 8 + db) * 128 + lane * 4]) =
                make_float4(oacc[db][0], oacc[db][1], oacc[db][2], oacc[db][3]);
    }
    __syncthreads();
    if (kq == 0 && outp) {
        #pragma unroll
        for (int db = 0; db < 8; db++) {
            float4 r1 = *(float4*)(&Red[((mi3 * 3 + 0) * 8 + db) * 128 + lane * 4]);
            float4 r2 = *(float4*)(&Red[((mi3 * 3 + 1) * 8 + db) * 128 + lane * 4]);
            float4 r3 = *(float4*)(&Red[((mi3 * 3 + 2) * 8 + db) * 128 + lane * 4]);
            const int m = mi3 * 16 + g;
            float* ob = outp + ((size_t)bh * Mc + m0 + m) * Dc + db * 8 + 2 * t;
            *(float2*)ob = make_float2(oacc[db][0] + r1.x + r2.x + r3.x,
                                       oacc[db][1] + r1.y + r2.y + r3.y);
            *(float2*)(ob + 8 * Dc) = make_float2(oacc[db][2] + r1.z + r2.z + r3.z,
                                                  oacc[db][3] + r1.w + r2.w + r3.w);
        }
    }
}

extern "C" void kernel_launch(void* const* d_in, const int* in_sizes, int n_in,
                              void* d_out, int out_size)
{
    const float* q    = (const float*)d_in[0];
    const float* k    = (const float*)d_in[1];
    const float* v    = (const float*)d_in[2];
    const int*   mask = (const int*)d_in[3];

    float* outp = nullptr;
    float* pp   = nullptr;
    long long osz = (long long)out_size;
    if (osz >= OUT_ELEMS + P_ELEMS) {            // (out, p_attn) concatenated
        outp = (float*)d_out;
        pp   = (float*)d_out + OUT_ELEMS;
    } else {                                     // p_attn only
        pp   = (float*)d_out;
    }

    cudaFuncSetAttribute(attn_tc_kernel,
                         cudaFuncAttributeMaxDynamicSharedMemorySize,
                         (int)SMEM_BYTES);

    dim3 grid(BHc * (Mc / MT));   // 4096 CTAs; consecutive CTAs share (b,h) -> K/V L2 reuse
    attn_tc_kernel<<<grid, THREADS, SMEM_BYTES>>>(q, k, v, mask, outp, pp);
}

// round 8
// speedup vs baseline: 1.6389x; 1.0027x over previous
#include <cuda_runtime.h>
#include <cstdint>

// Problem shape (fixed by the dataset)
constexpr int Bc = 8, Hc = 16, Mc = 1024, Nc = 1024, Dc = 64;
constexpr int BHc = Bc * Hc;
constexpr long long OUT_ELEMS = (long long)BHc * Mc * Dc;   // 8,388,608
constexpr long long P_ELEMS   = (long long)BHc * Mc * Nc;   // 134,217,728

constexpr int MT = 32;        // M rows per CTA
constexpr int NTILE = 128;    // K/V/P rows (cols) per staged block
constexpr int THREADS = 256;  // 8 warps, 3 CTAs/SM

// smem pitches (floats) for conflict-free fragment access:
//  "(row g)*pitch + t" pattern needs pitch%32==4  (banks 4g+t distinct)
//  "(row t)*pitch + g" pattern needs pitch%32==8  (banks 8t+g distinct)
constexpr int KP = 68;   // K tile (also Q staging)
constexpr int VP = 72;   // V tile
constexpr int PP = 132;  // P block (132 % 32 == 4)

constexpr int KV_OFF = 0;                      // 128*72 = 9216 floats (K/V tile; Red alias)
constexpr int P_OFF  = KV_OFF + NTILE * VP;    // 32*132 = 4224 floats (P block / unused ph1)
constexpr int MSK_OFF = P_OFF + MT * PP;       // 1024 ints
constexpr int SMEM_FLOATS = MSK_OFF + Nc;      // 14464
constexpr size_t SMEM_BYTES = (size_t)SMEM_FLOATS * 4;   // 57,856 B -> 3 CTAs/SM

#define NEG_INF_F (-1e9f)

__device__ __forceinline__ uint32_t tf32_hi(float x) {
    uint32_t h;
    asm("cvt.rna.tf32.f32 %0, %1;" : "=r"(h) : "f"(x));
    return h;
}

__device__ __forceinline__ void tf32_split(float x, uint32_t& h, uint32_t& l) {
    asm("cvt.rna.tf32.f32 %0, %1;" : "=r"(h) : "f"(x));
    float hf = __uint_as_float(h);
    float r  = x - hf;
    asm("cvt.rna.tf32.f32 %0, %1;" : "=r"(l) : "f"(r));
}

__device__ __forceinline__ void mma_tf32(float* c, const uint32_t* a, uint32_t b0, uint32_t b1) {
    asm volatile(
        "mma.sync.aligned.m16n8k8.row.col.f32.tf32.tf32.f32 "
        "{%0,%1,%2,%3}, {%4,%5,%6,%7}, {%8,%9}, {%0,%1,%2,%3};\n"
        : "+f"(c[0]), "+f"(c[1]), "+f"(c[2]), "+f"(c[3])
        : "r"(a[0]), "r"(a[1]), "r"(a[2]), "r"(a[3]), "r"(b0), "r"(b1));
}

__global__ __launch_bounds__(THREADS, 3)
void attn_tc_kernel(const float* __restrict__ q,
                    const float* __restrict__ k,
                    const float* __restrict__ v,
                    const int*   __restrict__ mask,
                    float* __restrict__ outp,   // may be null
                    float* __restrict__ pp)     // S scratch + p_attn output
{
    extern __shared__ float smem[];
    float* KV  = smem + KV_OFF;    // K tile [128][KP] / V tile [128][VP] / Red alias
    float* Pb  = smem + P_OFF;     // P block [MT][PP] (phase 3)
    int*   Msk = (int*)(smem + MSK_OFF);

    const int mtiles = Mc / MT;
    const int bh = blockIdx.x / mtiles;
    const int m0 = (blockIdx.x % mtiles) * MT;
    const int tid  = threadIdx.x;
    const int wid  = tid >> 5;       // 0..7
    const int lane = tid & 31;
    const int g = lane >> 2;         // 0..7
    const int t = lane & 3;          // 0..3

    const float scale = 1.0f / 32.0f;  // 1/sqrt(N=1024), faithful to the source bug

    float* Sbase = pp + ((size_t)bh * Mc + m0) * Nc;   // this CTA's 32 rows of p_attn

    #pragma unroll
    for (int i = 0; i < Nc / THREADS; i++)
        Msk[i * THREADS + tid] = mask[(size_t)bh * Nc + i * THREADS + tid];

    // ---- stage Q tile into KV (pitch KP), hoist Q-hi fragments to registers ----
    {
        const float4* qg = (const float4*)(q + (size_t)(bh * Mc + m0) * Dc);
        #pragma unroll
        for (int i = 0; i < (MT * Dc / 4) / THREADS; i++) {
            int f4 = i * THREADS + tid;
            float4 val = qg[f4];
            int row = f4 >> 4;          // 16 float4 per 64-float row
            int c   = (f4 & 15) * 4;
            *(float4*)(KV + row * KP + c) = val;
        }
    }
    __syncthreads();

    // warp = (mi, nbp): mi = m-half (16 rows), nbp -> n-slice [nbp*32,+32) per 128-block
    const int mi  = wid & 1;
    const int nbp = wid >> 1;

    uint32_t ah[8][4];   // Q-hi fragments, full k=64
    {
        const float* qs = KV + (mi * 16) * KP;
        #pragma unroll
        for (int kc = 0; kc < 8; kc++) {
            ah[kc][0] = tf32_hi(qs[g * KP + kc * 8 + t]);
            ah[kc][1] = tf32_hi(qs[(g + 8) * KP + kc * 8 + t]);
            ah[kc][2] = tf32_hi(qs[g * KP + kc * 8 + t + 4]);
            ah[kc][3] = tf32_hi(qs[(g + 8) * KP + kc * 8 + t + 4]);
        }
    }

    // =================== phase 1: S = mask(scale(Q K^T)), 2xTF32 ===============
    const float* kbase = k + (size_t)bh * Nc * Dc;
    #pragma unroll 1
    for (int nt = 0; nt < Nc / NTILE; nt++) {
        __syncthreads();
        {   // stage K tile [128][64] -> KV pitch KP (coalesced)
            const float4* kg = (const float4*)(kbase + (size_t)nt * NTILE * Dc);
            #pragma unroll
            for (int i = 0; i < (NTILE * Dc / 4) / THREADS; i++) {
                int f4 = i * THREADS + tid;
                float4 val = kg[f4];
                int row = f4 >> 4;
                int c   = (f4 & 15) * 4;
                *(float4*)(KV + row * KP + c) = val;
            }
        }
        __syncthreads();

        float acc[4][4] = {};   // [nb][frag]
        #pragma unroll
        for (int kc = 0; kc < 8; kc++) {
            #pragma unroll
            for (int nb = 0; nb < 4; nb++) {
                const float* kb = KV + (nbp * 32 + nb * 8 + g) * KP + kc * 8;
                uint32_t bh0, bl0, bh1, bl1;
                tf32_split(kb[t],     bh0, bl0);
                tf32_split(kb[t + 4], bh1, bl1);
                mma_tf32(acc[nb], ah[kc], bh0, bh1);   // q_hi * k_hi
                mma_tf32(acc[nb], ah[kc], bl0, bl1);   // q_hi * k_lo
            }
        }
        #pragma unroll
        for (int nb = 0; nb < 4; nb++) {
            const int m = mi * 16 + g;
            const int n = nt * NTILE + nbp * 32 + nb * 8 + 2 * t;
            const bool ok0 = Msk[n] != 0;
            const bool ok1 = Msk[n + 1] != 0;
            float s00 = ok0 ? acc[nb][0] * scale : NEG_INF_F;
            float s01 = ok1 ? acc[nb][1] * scale : NEG_INF_F;
            float s10 = ok0 ? acc[nb][2] * scale : NEG_INF_F;
            float s11 = ok1 ? acc[nb][3] * scale : NEG_INF_F;
            *(float2*)(Sbase + (size_t)m * Nc + n)       = make_float2(s00, s01);
            *(float2*)(Sbase + (size_t)(m + 8) * Nc + n) = make_float2(s10, s11);
        }
    }
    __syncthreads();

    // =================== phase 2: register-resident softmax (rows in L2) =======
    // warp wid owns rows wid*4 .. wid*4+3
    #pragma unroll 1
    for (int rr = 0; rr < 4; rr++) {
        const int m = wid * 4 + rr;
        float* prow = Sbase + (size_t)m * Nc;
        float r[32];
        float mx = NEG_INF_F;
        #pragma unroll
        for (int i = 0; i < 32; i++) {
            r[i] = prow[i * 32 + lane];
            mx = fmaxf(mx, r[i]);
        }
        #pragma unroll
        for (int o = 16; o; o >>= 1) mx = fmaxf(mx, __shfl_xor_sync(0xffffffffu, mx, o));
        float sum = 0.0f;
        #pragma unroll
        for (int i = 0; i < 32; i++) { r[i] = __expf(r[i] - mx); sum += r[i]; }
        #pragma unroll
        for (int o = 16; o; o >>= 1) sum += __shfl_xor_sync(0xffffffffu, sum, o);
        const float inv = 1.0f / sum;
        #pragma unroll
        for (int i = 0; i < 32; i++)
            prow[i * 32 + lane] = r[i] * inv;   // final p_attn, coalesced
    }
    __syncthreads();

    // =================== phase 3: out = P V (2xTF32, k-quarter split) ==========
    // warp = (mi3, kq): mi3 = m-half, kq = k-quarter of each 128-block; full d=64
    const int mi3 = wid & 1;
    const int kq  = wid >> 1;
    const float* vbase = v + (size_t)bh * Nc * Dc;

    float oacc[8][4] = {};   // [db][frag]
    #pragma unroll 1
    for (int nt = 0; nt < Nc / NTILE; nt++) {
        __syncthreads();
        {   // stage V tile [128][64] -> KV pitch VP (coalesced)
            const float4* vg = (const float4*)(vbase + (size_t)nt * NTILE * Dc);
            #pragma unroll
            for (int i = 0; i < (NTILE * Dc / 4) / THREADS; i++) {
                int f4 = i * THREADS + tid;
                float4 val = vg[f4];
                int row = f4 >> 4;
                int c   = (f4 & 15) * 4;
                *(float4*)(KV + row * VP + c) = val;
            }
        }
        {   // stage P block [32 rows][128 cols] -> Pb pitch PP (coalesced L2 reads)
            #pragma unroll
            for (int i = 0; i < (MT * NTILE / 4) / THREADS; i++) {
                int f4 = i * THREADS + tid;
                int row = f4 >> 5;          // 32 float4 per 128-col row
                int c   = (f4 & 31) * 4;
                float4 val = *(const float4*)(Sbase + (size_t)row * Nc + nt * NTILE + c);
                *(float4*)(Pb + row * PP + c) = val;
            }
        }
        __syncthreads();

        #pragma unroll
        for (int kc = 0; kc < 4; kc++) {
            const int kk = kq * 32 + kc * 8;   // row within staged block
            const float* pb = Pb + (mi3 * 16 + g) * PP + kk;
            uint32_t pah[4], pal[4];
            tf32_split(pb[t],              pah[0], pal[0]);
            tf32_split(pb[8 * PP + t],     pah[1], pal[1]);
            tf32_split(pb[t + 4],          pah[2], pal[2]);
            tf32_split(pb[8 * PP + t + 4], pah[3], pal[3]);
            #pragma unroll
            for (int db = 0; db < 8; db++) {
                const int base = (kk + t) * VP + db * 8 + g;
                uint32_t vh0 = tf32_hi(KV[base]);
                uint32_t vh1 = tf32_hi(KV[base + 4 * VP]);
                mma_tf32(oacc[db], pah, vh0, vh1);   // p_hi * v_hi
                mma_tf32(oacc[db], pal, vh0, vh1);   // p_lo * v_hi
            }
        }
    }
    __syncthreads();
    // k-quarter reduce through Red (aliases KV; V tile dead now)
    float* Red = KV;
    if (kq != 0) {
        #pragma unroll
        for (int db = 0; db < 8; db++)
            *(float4*)(&Red[((mi3 * 3 + (kq - 1)) * 8 + db) * 128 + lane * 4]) =
                make_float4(oacc[db][0], oacc[db][1], oacc[db][2], oacc[db][3]);
    }
    __syncthreads();
    if (kq == 0 && outp) {
        #pragma unroll
        for (int db = 0; db < 8; db++) {
            float4 r1 = *(float4*)(&Red[((mi3 * 3 + 0) * 8 + db) * 128 + lane * 4]);
            float4 r2 = *(float4*)(&Red[((mi3 * 3 + 1) * 8 + db) * 128 + lane * 4]);
            float4 r3 = *(float4*)(&Red[((mi3 * 3 + 2) * 8 + db) * 128 + lane * 4]);
            const int m = mi3 * 16 + g;
            float* ob = outp + ((size_t)bh * Mc + m0 + m) * Dc + db * 8 + 2 * t;
            *(float2*)ob = make_float2(oacc[db][0] + r1.x + r2.x + r3.x,
                                       oacc[db][1] + r1.y + r2.y + r3.y);
            *(float2*)(ob + 8 * Dc) = make_float2(oacc[db][2] + r1.z + r2.z + r3.z,
                                                  oacc[db][3] + r1.w + r2.w + r3.w);
        }
    }
}

extern "C" void kernel_launch(void* const* d_in, const int* in_sizes, int n_in,
                              void* d_out, int out_size)
{
    const float* q    = (const float*)d_in[0];
    const float* k    = (const float*)d_in[1];
    const float* v    = (const float*)d_in[2];
    const int*   mask = (const int*)d_in[3];

    float* outp = nullptr;
    float* pp   = nullptr;
    long long osz = (long long)out_size;
    if (osz >= OUT_ELEMS + P_ELEMS) {            // (out, p_attn) concatenated
        outp = (float*)d_out;
        pp   = (float*)d_out + OUT_ELEMS;
    } else {                                     // p_attn only
        pp   = (float*)d_out;
    }

    cudaFuncSetAttribute(attn_tc_kernel,
                         cudaFuncAttributeMaxDynamicSharedMemorySize,
                         (int)SMEM_BYTES);

    dim3 grid(BHc * (Mc / MT));   // 4096 CTAs; consecutive CTAs share (b,h) -> K/V L2 reuse
    attn_tc_kernel<<<grid, THREADS, SMEM_BYTES>>>(q, k, v, mask, outp, pp);
}